// round 1
// baseline (speedup 1.0000x reference)
#include <cuda_runtime.h>

#define D_MODEL 1024
#define N_HEADS 16
#define HD      64
#define T_SEQ   2048
#define BATCH   2
#define M_ROWS  (BATCH * T_SEQ)   // 4096

// ---------------------------------------------------------------------------
// Scratch (device globals; no allocation allowed)
// ---------------------------------------------------------------------------
__device__ float g_Q[BATCH * N_HEADS * T_SEQ * HD];   // [b,h,t,d]
__device__ float g_K[BATCH * N_HEADS * T_SEQ * HD];
__device__ float g_V[BATCH * N_HEADS * T_SEQ * HD];
__device__ float g_att[BATCH * T_SEQ * D_MODEL];      // [b,t,h*64+d]

// ---------------------------------------------------------------------------
// Tiled fp32 GEMM: Y[M,N] = X[M,K] @ W[N,K]^T + bias[N]
// BM=BN=128, BK=8, 256 threads, 8x8 microtile per thread.
// qkv_layout: scatter output to [b,h,t,d]; else plain row-major [M,N].
// ---------------------------------------------------------------------------
__device__ __forceinline__ void gemm_body(const float* __restrict__ X,
                                          const float* __restrict__ W,
                                          const float* __restrict__ bias,
                                          float* __restrict__ Y,
                                          bool qkv_layout)
{
    __shared__ float Xs[8][128];
    __shared__ float Ws[8][128];

    const int m0  = blockIdx.y * 128;
    const int n0  = blockIdx.x * 128;
    const int tid = threadIdx.x;
    const int ty  = tid >> 4;        // 0..15
    const int tx  = tid & 15;        // 0..15
    const int lr  = tid >> 1;        // 0..127 (load row)
    const int lc  = (tid & 1) * 4;   // 0 or 4 (load col group)

    const float* Xp = X + (size_t)(m0 + lr) * D_MODEL + lc;
    const float* Wp = W + (size_t)(n0 + lr) * D_MODEL + lc;

    float acc[8][8];
#pragma unroll
    for (int i = 0; i < 8; i++)
#pragma unroll
        for (int j = 0; j < 8; j++) acc[i][j] = 0.f;

    for (int kt = 0; kt < D_MODEL; kt += 8) {
        float4 xv = *(const float4*)(Xp + kt);
        float4 wv = *(const float4*)(Wp + kt);
        __syncthreads();
        Xs[lc + 0][lr] = xv.x; Xs[lc + 1][lr] = xv.y;
        Xs[lc + 2][lr] = xv.z; Xs[lc + 3][lr] = xv.w;
        Ws[lc + 0][lr] = wv.x; Ws[lc + 1][lr] = wv.y;
        Ws[lc + 2][lr] = wv.z; Ws[lc + 3][lr] = wv.w;
        __syncthreads();
#pragma unroll
        for (int kk = 0; kk < 8; kk++) {
            float af[8], bf[8];
            *(float4*)(af)     = *(const float4*)&Xs[kk][ty * 8];
            *(float4*)(af + 4) = *(const float4*)&Xs[kk][ty * 8 + 4];
            *(float4*)(bf)     = *(const float4*)&Ws[kk][tx * 8];
            *(float4*)(bf + 4) = *(const float4*)&Ws[kk][tx * 8 + 4];
#pragma unroll
            for (int i = 0; i < 8; i++)
#pragma unroll
                for (int j = 0; j < 8; j++)
                    acc[i][j] += af[i] * bf[j];
        }
    }

    float bfr[8];
#pragma unroll
    for (int j = 0; j < 8; j++) bfr[j] = bias[n0 + tx * 8 + j];

    if (qkv_layout) {
        const int nbase = n0 + tx * 8;
        const int h = nbase >> 6;
        const int d = nbase & 63;
#pragma unroll
        for (int i = 0; i < 8; i++) {
            int m  = m0 + ty * 8 + i;
            int bb = m >> 11;            // / 2048
            int t  = m & (T_SEQ - 1);
            float* dst = Y + (((size_t)bb * N_HEADS + h) * T_SEQ + t) * HD + d;
            float4 o0 = make_float4(acc[i][0] + bfr[0], acc[i][1] + bfr[1],
                                    acc[i][2] + bfr[2], acc[i][3] + bfr[3]);
            float4 o1 = make_float4(acc[i][4] + bfr[4], acc[i][5] + bfr[5],
                                    acc[i][6] + bfr[6], acc[i][7] + bfr[7]);
            *(float4*)(dst)     = o0;
            *(float4*)(dst + 4) = o1;
        }
    } else {
#pragma unroll
        for (int i = 0; i < 8; i++) {
            int m = m0 + ty * 8 + i;
            float* dst = Y + (size_t)m * D_MODEL + n0 + tx * 8;
            float4 o0 = make_float4(acc[i][0] + bfr[0], acc[i][1] + bfr[1],
                                    acc[i][2] + bfr[2], acc[i][3] + bfr[3]);
            float4 o1 = make_float4(acc[i][4] + bfr[4], acc[i][5] + bfr[5],
                                    acc[i][6] + bfr[6], acc[i][7] + bfr[7]);
            *(float4*)(dst)     = o0;
            *(float4*)(dst + 4) = o1;
        }
    }
}

__global__ void __launch_bounds__(256)
qkv_kernel(const float* __restrict__ X,
           const float* __restrict__ Wq, const float* __restrict__ bq,
           const float* __restrict__ Wk, const float* __restrict__ bk,
           const float* __restrict__ Wv, const float* __restrict__ bv)
{
    int z = blockIdx.z;
    const float* W    = (z == 0) ? Wq : (z == 1) ? Wk : Wv;
    const float* bias = (z == 0) ? bq : (z == 1) ? bk : bv;
    float* Y          = (z == 0) ? g_Q : (z == 1) ? g_K : g_V;
    gemm_body(X, W, bias, Y, true);
}

__global__ void __launch_bounds__(256)
out_kernel(const float* __restrict__ Wo, const float* __restrict__ bo,
           float* __restrict__ out)
{
    gemm_body(g_att, Wo, bo, out, false);
}

// ---------------------------------------------------------------------------
// Flash-style causal attention with positional decay:
//   s(i,j) = (q_i . k_j)/8 - (i-j)   for j <= i, else masked.
// 64 (q rows) x 64 (kv cols) tiles, 256 threads, 4x4 microtile per thread.
// Q,K stored k-major (transposed) in smem for float4 score-phase loads.
// P overlays K's smem region.
// ---------------------------------------------------------------------------
#define KS 68   // k-major stride (float4-aligned, bank-skewed)

__global__ void __launch_bounds__(256) attn_kernel()
{
    extern __shared__ float sm[];
    float* QsT = sm;                 // [64 k][KS] (cols = q rows)
    float* KsT = sm + 64 * KS;       // [64 k][KS] (cols = kv rows); reused as Ps
    float* Vs  = sm + 2 * 64 * KS;   // [64 kv][64 d]
    float* Ps  = KsT;                // stride 65: [64 qrow][64 kvcol]

    const int tid = threadIdx.x;
    const int tr  = tid >> 4;        // 0..15 row-tile
    const int tc  = tid & 15;        // 0..15 col-tile
    const int bh  = blockIdx.y;      // 0..31
    const int ib  = (int)gridDim.x - 1 - (int)blockIdx.x;  // long blocks first
    const int i0  = ib * 64;

    const float* Qg = g_Q + (size_t)bh * T_SEQ * HD;
    const float* Kg = g_K + (size_t)bh * T_SEQ * HD;
    const float* Vg = g_V + (size_t)bh * T_SEQ * HD;

    // Load Q block transposed (k-major)
#pragma unroll
    for (int rep = 0; rep < 4; rep++) {
        int idx = tid + rep * 256;
        int r = idx >> 4;
        int c = (idx & 15) << 2;
        float4 v = *(const float4*)(Qg + (size_t)(i0 + r) * HD + c);
        QsT[(c + 0) * KS + r] = v.x;
        QsT[(c + 1) * KS + r] = v.y;
        QsT[(c + 2) * KS + r] = v.z;
        QsT[(c + 3) * KS + r] = v.w;
    }

    float m[4], l[4], acc[4][4];
#pragma unroll
    for (int i = 0; i < 4; i++) {
        m[i] = -1e30f; l[i] = 0.f;
#pragma unroll
        for (int j = 0; j < 4; j++) acc[i][j] = 0.f;
    }

    const float inv_s = 0.125f;  // 1/sqrt(64)

    for (int j0 = 0; j0 <= i0; j0 += 64) {
        __syncthreads();  // previous iter done with KsT/Ps/Vs (also orders Q load)
        // Load K transposed + V natural
#pragma unroll
        for (int rep = 0; rep < 4; rep++) {
            int idx = tid + rep * 256;
            int r = idx >> 4;
            int c = (idx & 15) << 2;
            float4 kv = *(const float4*)(Kg + (size_t)(j0 + r) * HD + c);
            KsT[(c + 0) * KS + r] = kv.x;
            KsT[(c + 1) * KS + r] = kv.y;
            KsT[(c + 2) * KS + r] = kv.z;
            KsT[(c + 3) * KS + r] = kv.w;
            float4 vv = *(const float4*)(Vg + (size_t)(j0 + r) * HD + c);
            *(float4*)(Vs + r * 64 + c) = vv;
        }
        __syncthreads();

        // Scores: s[4][4] = Q_tile . K_tile^T
        float s[4][4];
#pragma unroll
        for (int i = 0; i < 4; i++)
#pragma unroll
            for (int j = 0; j < 4; j++) s[i][j] = 0.f;

#pragma unroll 8
        for (int k = 0; k < 64; k++) {
            float af[4], bf[4];
            *(float4*)af = *(const float4*)(QsT + k * KS + tr * 4);
            *(float4*)bf = *(const float4*)(KsT + k * KS + tc * 4);
#pragma unroll
            for (int ii = 0; ii < 4; ii++)
#pragma unroll
                for (int jj = 0; jj < 4; jj++)
                    s[ii][jj] += af[ii] * bf[jj];
        }

        // Mask + decay + online softmax update
#pragma unroll
        for (int ii = 0; ii < 4; ii++) {
            int ig = i0 + tr * 4 + ii;
            float rowmax = -1e30f;
#pragma unroll
            for (int jj = 0; jj < 4; jj++) {
                int jg = j0 + tc * 4 + jj;
                float v = (jg > ig) ? -1e30f
                                    : s[ii][jj] * inv_s - (float)(ig - jg);
                s[ii][jj] = v;
                rowmax = fmaxf(rowmax, v);
            }
            rowmax = fmaxf(rowmax, __shfl_xor_sync(0xffffffffu, rowmax, 1));
            rowmax = fmaxf(rowmax, __shfl_xor_sync(0xffffffffu, rowmax, 2));
            rowmax = fmaxf(rowmax, __shfl_xor_sync(0xffffffffu, rowmax, 4));
            rowmax = fmaxf(rowmax, __shfl_xor_sync(0xffffffffu, rowmax, 8));
            float mn    = fmaxf(m[ii], rowmax);
            float scale = __expf(m[ii] - mn);
            m[ii] = mn;
            l[ii] *= scale;
            float psum = 0.f;
#pragma unroll
            for (int jj = 0; jj < 4; jj++) {
                float p = __expf(s[ii][jj] - mn);
                s[ii][jj] = p;
                psum += p;
            }
            l[ii] += psum;
#pragma unroll
            for (int jj = 0; jj < 4; jj++) acc[ii][jj] *= scale;
        }

        __syncthreads();  // done reading KsT as K
        // Write P (overlaying K's smem), stride 65
#pragma unroll
        for (int ii = 0; ii < 4; ii++)
#pragma unroll
            for (int jj = 0; jj < 4; jj++)
                Ps[(tr * 4 + ii) * 65 + tc * 4 + jj] = s[ii][jj];
        __syncthreads();

        // O accumulation: acc += P @ V
#pragma unroll 4
        for (int j = 0; j < 64; j++) {
            float pa[4];
#pragma unroll
            for (int ii = 0; ii < 4; ii++) pa[ii] = Ps[(tr * 4 + ii) * 65 + j];
            float vb[4];
            *(float4*)vb = *(const float4*)(Vs + j * 64 + tc * 4);
#pragma unroll
            for (int ii = 0; ii < 4; ii++)
#pragma unroll
                for (int jj = 0; jj < 4; jj++)
                    acc[ii][jj] += pa[ii] * vb[jj];
        }
    }

    // Final: reduce l across the 16-thread row group, normalize, store
    const int b = bh >> 4;
    const int h = bh & 15;
#pragma unroll
    for (int ii = 0; ii < 4; ii++) {
        float lr = l[ii];
        lr += __shfl_xor_sync(0xffffffffu, lr, 1);
        lr += __shfl_xor_sync(0xffffffffu, lr, 2);
        lr += __shfl_xor_sync(0xffffffffu, lr, 4);
        lr += __shfl_xor_sync(0xffffffffu, lr, 8);
        float inv = 1.0f / lr;
        int ig = i0 + tr * 4 + ii;
        float4 o = make_float4(acc[ii][0] * inv, acc[ii][1] * inv,
                               acc[ii][2] * inv, acc[ii][3] * inv);
        *(float4*)(g_att + ((size_t)b * T_SEQ + ig) * D_MODEL + h * HD + tc * 4) = o;
    }
}

// ---------------------------------------------------------------------------
// Launch
// ---------------------------------------------------------------------------
extern "C" void kernel_launch(void* const* d_in, const int* in_sizes, int n_in,
                              void* d_out, int out_size)
{
    const float* x  = (const float*)d_in[0];
    const float* Wq = (const float*)d_in[1];
    const float* bq = (const float*)d_in[2];
    const float* Wk = (const float*)d_in[3];
    const float* bk = (const float*)d_in[4];
    const float* Wv = (const float*)d_in[5];
    const float* bv = (const float*)d_in[6];
    const float* Wo = (const float*)d_in[7];
    const float* bo = (const float*)d_in[8];
    float* out = (float*)d_out;

    // QKV projections (fused grid over z = {Q,K,V})
    dim3 gq(D_MODEL / 128, M_ROWS / 128, 3);
    qkv_kernel<<<gq, 256>>>(x, Wq, bq, Wk, bk, Wv, bv);

    // Attention
    const int ATT_SMEM = (2 * 64 * KS + 64 * 64) * (int)sizeof(float);  // 51200 B
    cudaFuncSetAttribute(attn_kernel,
                         cudaFuncAttributeMaxDynamicSharedMemorySize, ATT_SMEM);
    dim3 ga(T_SEQ / 64, BATCH * N_HEADS);
    attn_kernel<<<ga, 256, ATT_SMEM>>>();

    // Output projection
    dim3 go(D_MODEL / 128, M_ROWS / 128);
    out_kernel<<<go, 256>>>(Wo, bo, out);
}